// round 10
// baseline (speedup 1.0000x reference)
#include <cuda_runtime.h>
#include <cuda_bf16.h>
#include <cstdint>

static constexpr int NODES = 50000;
static constexpr int EDGES = 400000;
static constexpr float LNE = 1e-5f;

__device__ float g_agg[(size_t)NODES * 192];
__device__ int g_cnt[NODES];
__device__ int g_off[NODES];
__device__ int g_cur[NODES];
__device__ int g_srcs[EDGES];

// ---------------- smem layout (bytes) ----------------
static constexpr int PAR_OFF = 0;               // 768 floats (b1,g1,be1,b2,g2,be2)
static constexpr int RED_OFF = 3072;            // 256 float2 (LN partial sums)
static constexpr int AH_OFF  = 5120;            // A hi (max 128 x 400B)
static constexpr int AL_OFF  = AH_OFF + 51200;  // A lo
static constexpr int BH_OFF  = AL_OFF + 51200;  // B hi (max 192 x 272B)
static constexpr int BL_OFF  = BH_OFF + 52224;  // B lo
static constexpr int SM_TOTAL = BL_OFF + 52224; // 211968 B
static constexpr int SB = 272;                  // B row stride (128*2 + 16)
static constexpr int SU = 272;                  // U row stride

// ---------------- helpers ----------------
__device__ __forceinline__ uint32_t smem_u32(const void* p) {
    uint32_t a;
    asm("{ .reg .u64 t; cvta.to.shared.u64 t, %1; cvt.u32.u64 %0, t; }" : "=r"(a) : "l"(p));
    return a;
}
__device__ __forceinline__ void split2(float a, float b, uint32_t& hi, uint32_t& lo) {
    __nv_bfloat16 ah = __float2bfloat16_rn(a), bh = __float2bfloat16_rn(b);
    float ar = a - __bfloat162float(ah), br = b - __bfloat162float(bh);
    __nv_bfloat16 al = __float2bfloat16_rn(ar), bl = __float2bfloat16_rn(br);
    hi = (uint32_t)__bfloat16_as_ushort(ah) | ((uint32_t)__bfloat16_as_ushort(bh) << 16);
    lo = (uint32_t)__bfloat16_as_ushort(al) | ((uint32_t)__bfloat16_as_ushort(bl) << 16);
}
__device__ __forceinline__ void ldsm4(uint32_t* r, uint32_t addr) {
    asm volatile("ldmatrix.sync.aligned.m8n8.x4.shared.b16 {%0,%1,%2,%3}, [%4];"
                 : "=r"(r[0]), "=r"(r[1]), "=r"(r[2]), "=r"(r[3]) : "r"(addr));
}
__device__ __forceinline__ void ldsm4t(uint32_t* r, uint32_t addr) {
    asm volatile("ldmatrix.sync.aligned.m8n8.x4.trans.shared.b16 {%0,%1,%2,%3}, [%4];"
                 : "=r"(r[0]), "=r"(r[1]), "=r"(r[2]), "=r"(r[3]) : "r"(addr));
}
__device__ __forceinline__ void mma16816(float* d, const uint32_t* a, const uint32_t* b) {
    asm volatile("mma.sync.aligned.m16n8k16.row.col.f32.bf16.bf16.f32 "
                 "{%0,%1,%2,%3}, {%4,%5,%6,%7}, {%8,%9}, {%0,%1,%2,%3};"
                 : "+f"(d[0]), "+f"(d[1]), "+f"(d[2]), "+f"(d[3])
                 : "r"(a[0]), "r"(a[1]), "r"(a[2]), "r"(a[3]), "r"(b[0]), "r"(b[1]));
}

// 3-pass bf16-split GEMM: D[128x128] += A[128xK] * B[KxN=128]
__device__ __forceinline__ void gemm3(float acc[2][8][4], uint32_t sbase,
                                      int sa, int ksteps, int m0, int n0, int lane)
{
    const uint32_t aoff = (uint32_t)((lane & 15) * sa + (lane >> 4) * 16);
    const uint32_t boff = (uint32_t)((lane & 15) * SB + (lane >> 4) * 16);
    for (int pass = 0; pass < 3; pass++) {
        uint32_t aAddr = sbase + ((pass == 1) ? AL_OFF : AH_OFF) + m0 * sa + aoff;
        uint32_t bAddr = sbase + ((pass == 2) ? BL_OFF : BH_OFF) + n0 * 2 + boff;
        for (int ks = 0; ks < ksteps; ks++) {
            uint32_t a0[4], a1[4], bf[8][2], r[4];
            ldsm4(a0, aAddr);
            ldsm4(a1, aAddr + 16 * sa);
#pragma unroll
            for (int bt = 0; bt < 4; bt++) {
                ldsm4t(r, bAddr + bt * 32);
                bf[2 * bt][0] = r[0]; bf[2 * bt][1] = r[1];
                bf[2 * bt + 1][0] = r[2]; bf[2 * bt + 1][1] = r[3];
            }
#pragma unroll
            for (int nt = 0; nt < 8; nt++) {
                mma16816(acc[0][nt], a0, bf[nt]);
                mma16816(acc[1][nt], a1, bf[nt]);
            }
            aAddr += 32;       // 16 k-cols * 2B
            bAddr += 16 * SB;  // 16 k-rows
        }
    }
}

// stage weights W[rows][128] -> B hi/lo smem
__device__ __forceinline__ void stage_w(char* smem, const float* __restrict__ W,
                                        int rows, int tid)
{
    for (int idx = tid; idx < rows * 32; idx += 256) {
        int k = idx >> 5, c = (idx & 31) * 4;
        float4 w = __ldg((const float4*)(W + (size_t)k * 128 + c));
        uint32_t h0, l0, h1, l1;
        split2(w.x, w.y, h0, l0);
        split2(w.z, w.w, h1, l1);
        char* p = smem + BH_OFF + k * SB + c * 2;
        *(uint32_t*)p = h0; *(uint32_t*)(p + 4) = h1;
        char* q = p + (BL_OFF - BH_OFF);
        *(uint32_t*)q = l0; *(uint32_t*)(q + 4) = l1;
    }
}

// bias add + LN stats (cross-half via smem); leaves biased values in acc
__device__ __forceinline__ void ln_stats(float acc[2][8][4], char* smem,
                                         const float* s_par, int parOff,
                                         int m0, int n0, int cg, int lane,
                                         float mean[2][2], float rstd[2][2])
{
    float2* s_red = (float2*)(smem + RED_OFF);
    const int grp = lane >> 2, qd = lane & 3;
#pragma unroll
    for (int mt = 0; mt < 2; mt++) {
        float sA = 0.f, qA = 0.f, sB = 0.f, qB = 0.f;
#pragma unroll
        for (int nt = 0; nt < 8; nt++) {
            int n = n0 + nt * 8 + qd * 2;
            float b0v = s_par[parOff + n], b1v = s_par[parOff + n + 1];
            float d0 = acc[mt][nt][0] + b0v, d1 = acc[mt][nt][1] + b1v;
            float d2 = acc[mt][nt][2] + b0v, d3 = acc[mt][nt][3] + b1v;
            acc[mt][nt][0] = d0; acc[mt][nt][1] = d1;
            acc[mt][nt][2] = d2; acc[mt][nt][3] = d3;
            sA += d0 + d1; qA = fmaf(d0, d0, fmaf(d1, d1, qA));
            sB += d2 + d3; qB = fmaf(d2, d2, fmaf(d3, d3, qB));
        }
#pragma unroll
        for (int o = 1; o <= 2; o <<= 1) {
            sA += __shfl_xor_sync(~0u, sA, o); qA += __shfl_xor_sync(~0u, qA, o);
            sB += __shfl_xor_sync(~0u, sB, o); qB += __shfl_xor_sync(~0u, qB, o);
        }
        if (qd == 0) {
            int rA = m0 + mt * 16 + grp;
            s_red[cg * 128 + rA]     = make_float2(sA, qA);
            s_red[cg * 128 + rA + 8] = make_float2(sB, qB);
        }
    }
    __syncthreads();
#pragma unroll
    for (int mt = 0; mt < 2; mt++)
#pragma unroll
        for (int h = 0; h < 2; h++) {
            int r = m0 + mt * 16 + grp + h * 8;
            float2 t0 = s_red[r], t1 = s_red[128 + r];
            float mu = (t0.x + t1.x) * (1.0f / 128.0f);
            float var = fmaf(-mu, mu, (t0.y + t1.y) * (1.0f / 128.0f));
            mean[mt][h] = mu;
            rstd[mt][h] = rsqrtf(var + LNE);
        }
}

// ---------------- CSR build + gather ----------------
__global__ __launch_bounds__(256) void zero_cnt_kernel() {
    int i = blockIdx.x * 256 + threadIdx.x;
    if (i < NODES) g_cnt[i] = 0;
}

__global__ __launch_bounds__(256) void hist_kernel(const int* __restrict__ ei) {
    int e = blockIdx.x * 256 + threadIdx.x;
    if (e < EDGES) atomicAdd(&g_cnt[__ldg(ei + EDGES + e)], 1);
}

__global__ __launch_bounds__(1024) void scan_kernel() {
    __shared__ int sp[1024];
    const int t = threadIdx.x;
    const int lo = t * 49;
    const int hi = min(lo + 49, NODES);
    int s = 0;
    for (int i = lo; i < hi; i++) s += g_cnt[i];
    sp[t] = s;
    __syncthreads();
    for (int off = 1; off < 1024; off <<= 1) {
        int v = (t >= off) ? sp[t - off] : 0;
        __syncthreads();
        sp[t] += v;
        __syncthreads();
    }
    int run = sp[t] - s;   // exclusive prefix of this thread's chunk
    for (int i = lo; i < hi; i++) {
        g_off[i] = run;
        g_cur[i] = run;
        run += g_cnt[i];
    }
}

__global__ __launch_bounds__(256) void permute_kernel(const int* __restrict__ ei) {
    int e = blockIdx.x * 256 + threadIdx.x;
    if (e >= EDGES) return;
    int src = __ldg(ei + e);
    int dst = __ldg(ei + EDGES + e);
    int slot = atomicAdd(&g_cur[dst], 1);
    g_srcs[slot] = src;
}

// one warp per node: agg[n] = sum_{s in inN(n)} concat(x,pos)[s]
__global__ __launch_bounds__(256) void gather_kernel(const float* __restrict__ x,
                                                     const float* __restrict__ pos) {
    int n = blockIdx.x * 8 + (threadIdx.x >> 5);
    if (n >= NODES) return;
    int lane = threadIdx.x & 31;
    int start = __ldg(&g_off[n]);
    int deg   = __ldg(&g_cnt[n]);

    float4 a4 = make_float4(0.f, 0.f, 0.f, 0.f);
    float2 a2 = make_float2(0.f, 0.f);
    for (int base = 0; base < deg; base += 32) {
        int cnt = min(32, deg - base);
        int my = (lane < cnt) ? __ldg(g_srcs + start + base + lane) : 0;
        for (int i = 0; i < cnt; i++) {
            int s = __shfl_sync(~0u, my, i);
            float4 v = __ldg((const float4*)x + (size_t)s * 32 + lane);
            float2 p = __ldg((const float2*)pos + (size_t)s * 32 + lane);
            a4.x += v.x; a4.y += v.y; a4.z += v.z; a4.w += v.w;
            a2.x += p.x; a2.y += p.y;
        }
    }
    *((float4*)(g_agg + (size_t)n * 192) + lane) = a4;
    *((float2*)(g_agg + (size_t)n * 192 + 128) + lane) = a2;
}

// ---------------- fused HMMA GIN (both branches via blockIdx.y) ----------------
__global__ __launch_bounds__(256, 1)
void gin_mma_kernel(const float* __restrict__ x, const float* __restrict__ pos,
                    const float* __restrict__ eps,  const float* __restrict__ W1,
                    const float* __restrict__ b1,   const float* __restrict__ g1,
                    const float* __restrict__ be1,  const float* __restrict__ W2,
                    const float* __restrict__ b2,   const float* __restrict__ lng,
                    const float* __restrict__ lnb,
                    const float* __restrict__ epsp, const float* __restrict__ W1p,
                    const float* __restrict__ b1p,  const float* __restrict__ g1p,
                    const float* __restrict__ be1p, const float* __restrict__ W2p,
                    const float* __restrict__ b2p,  const float* __restrict__ lnpg,
                    const float* __restrict__ lnpb,
                    float* __restrict__ out)
{
    extern __shared__ char smem[];
    const uint32_t sbase = smem_u32(smem);
    float* s_par = (float*)smem;
    const int tid = threadIdx.x, lane = tid & 31, wid = tid >> 5;
    const int m0 = (wid & 3) * 32, n0 = (wid >> 2) * 64, cg = wid >> 2;
    const int br = blockIdx.y;
    const int row0 = blockIdx.x * 128;

    const int din = br ? 64 : 192;
    const int sa1 = br ? 144 : 400;   // A row stride (din*2 + 16)
    const int ks1 = br ? 4 : 12;
    const float e1 = 1.0f + __ldg(br ? epsp : eps);
    const float* Wa = br ? W1p : W1;
    const float* Wb = br ? W2p : W2;
    float* outb = out + (br ? (size_t)NODES * 128 : 0);

    // stage LN / bias params
    {
        const float* pars[6] = { br ? b1p : b1, br ? g1p : g1, br ? be1p : be1,
                                 br ? b2p : b2, br ? lnpg : lng, br ? lnpb : lnb };
        for (int j = tid; j < 768; j += 256) s_par[j] = __ldg(pars[j >> 7] + (j & 127));
    }

    // stage A1 = (1+eps)*feat + agg   (bf16 hi/lo)
    {
        const int nf4 = din / 4;
        for (int idx = tid; idx < 128 * nf4; idx += 256) {
            int r = idx / nf4, c = (idx - r * nf4) * 4;
            int row = row0 + r;
            float4 f = make_float4(0.f, 0.f, 0.f, 0.f), a = f;
            if (row < NODES) {
                if (br == 0) {
                    f = (c < 128) ? __ldg((const float4*)(x + (size_t)row * 128 + c))
                                  : __ldg((const float4*)(pos + (size_t)row * 64 + (c - 128)));
                    a = __ldg((const float4*)(g_agg + (size_t)row * 192 + c));
                } else {
                    f = __ldg((const float4*)(pos + (size_t)row * 64 + c));
                    a = __ldg((const float4*)(g_agg + (size_t)row * 192 + 128 + c));
                }
            }
            float v0 = fmaf(e1, f.x, a.x), v1 = fmaf(e1, f.y, a.y);
            float v2 = fmaf(e1, f.z, a.z), v3 = fmaf(e1, f.w, a.w);
            uint32_t h0, l0, h1, l1;
            split2(v0, v1, h0, l0);
            split2(v2, v3, h1, l1);
            char* p = smem + AH_OFF + r * sa1 + c * 2;
            *(uint32_t*)p = h0; *(uint32_t*)(p + 4) = h1;
            char* q = p + (AL_OFF - AH_OFF);
            *(uint32_t*)q = l0; *(uint32_t*)(q + 4) = l1;
        }
    }
    stage_w(smem, Wa, din, tid);
    __syncthreads();

    // ---- GEMM1 ----
    float acc[2][8][4];
#pragma unroll
    for (int mt = 0; mt < 2; mt++)
#pragma unroll
        for (int nt = 0; nt < 8; nt++)
#pragma unroll
            for (int c = 0; c < 4; c++) acc[mt][nt][c] = 0.f;

    gemm3(acc, sbase, sa1, ks1, m0, n0, lane);
    __syncthreads();   // A/B regions free for reuse

    // ---- epilogue 1: LN + relu -> U (bf16 hi/lo in A region, stride 272) ----
    float mean[2][2], rstd[2][2];
    ln_stats(acc, smem, s_par, 0, m0, n0, cg, lane, mean, rstd);
    {
        const int grp = lane >> 2, qd = lane & 3;
#pragma unroll
        for (int mt = 0; mt < 2; mt++)
#pragma unroll
            for (int h = 0; h < 2; h++) {
                int r = m0 + mt * 16 + grp + h * 8;
                float mu = mean[mt][h], rs = rstd[mt][h];
#pragma unroll
                for (int nt = 0; nt < 8; nt++) {
                    int n = n0 + nt * 8 + qd * 2;
                    int ci = h * 2;
                    float d0 = acc[mt][nt][ci], d1 = acc[mt][nt][ci + 1];
                    float v0 = fmaf((d0 - mu) * rs, s_par[128 + n], s_par[256 + n]);
                    float v1 = fmaf((d1 - mu) * rs, s_par[128 + n + 1], s_par[256 + n + 1]);
                    v0 = fmaxf(v0, 0.f); v1 = fmaxf(v1, 0.f);
                    uint32_t hi, lo;
                    split2(v0, v1, hi, lo);
                    char* p = smem + AH_OFF + r * SU + n * 2;
                    *(uint32_t*)p = hi;
                    *(uint32_t*)(p + (AL_OFF - AH_OFF)) = lo;
                }
            }
    }
    stage_w(smem, Wb, 128, tid);
    __syncthreads();

    // ---- GEMM2 ----
#pragma unroll
    for (int mt = 0; mt < 2; mt++)
#pragma unroll
        for (int nt = 0; nt < 8; nt++)
#pragma unroll
            for (int c = 0; c < 4; c++) acc[mt][nt][c] = 0.f;

    gemm3(acc, sbase, SU, 8, m0, n0, lane);

    // ---- epilogue 2: LN + relu (+ residual) -> out ----
    ln_stats(acc, smem, s_par, 384, m0, n0, cg, lane, mean, rstd);
    {
        const int grp = lane >> 2, qd = lane & 3;
#pragma unroll
        for (int mt = 0; mt < 2; mt++)
#pragma unroll
            for (int h = 0; h < 2; h++) {
                int r = m0 + mt * 16 + grp + h * 8;
                int row = row0 + r;
                if (row >= NODES) continue;
                float mu = mean[mt][h], rs = rstd[mt][h];
#pragma unroll
                for (int nt = 0; nt < 8; nt++) {
                    int n = n0 + nt * 8 + qd * 2;
                    int ci = h * 2;
                    float d0 = acc[mt][nt][ci], d1 = acc[mt][nt][ci + 1];
                    float v0 = fmaf((d0 - mu) * rs, s_par[512 + n], s_par[640 + n]);
                    float v1 = fmaf((d1 - mu) * rs, s_par[512 + n + 1], s_par[640 + n + 1]);
                    v0 = fmaxf(v0, 0.f); v1 = fmaxf(v1, 0.f);
                    if (br == 0) {
                        float2 xv = *(const float2*)(x + (size_t)row * 128 + n);
                        v0 += xv.x; v1 += xv.y;
                    }
                    *(float2*)(outb + (size_t)row * 128 + n) = make_float2(v0, v1);
                }
            }
    }
}

// ---------------- launch ----------------
extern "C" void kernel_launch(void* const* d_in, const int* in_sizes, int n_in,
                              void* d_out, int out_size) {
    const float* x    = (const float*)d_in[0];
    const float* pos  = (const float*)d_in[1];
    const int*   ei   = (const int*)d_in[2];
    const float* eps  = (const float*)d_in[3];
    const float* W1   = (const float*)d_in[4];
    const float* b1   = (const float*)d_in[5];
    const float* g1   = (const float*)d_in[6];
    const float* be1  = (const float*)d_in[7];
    const float* W2   = (const float*)d_in[8];
    const float* b2   = (const float*)d_in[9];
    const float* lng  = (const float*)d_in[10];
    const float* lnb  = (const float*)d_in[11];
    const float* epsp = (const float*)d_in[12];
    const float* W1p  = (const float*)d_in[13];
    const float* b1p  = (const float*)d_in[14];
    const float* g1p  = (const float*)d_in[15];
    const float* be1p = (const float*)d_in[16];
    const float* W2p  = (const float*)d_in[17];
    const float* b2p  = (const float*)d_in[18];
    const float* lnpg = (const float*)d_in[19];
    const float* lnpb = (const float*)d_in[20];
    float* out = (float*)d_out;

    zero_cnt_kernel<<<(NODES + 255) / 256, 256>>>();
    hist_kernel<<<(EDGES + 255) / 256, 256>>>(ei);
    scan_kernel<<<1, 1024>>>();
    permute_kernel<<<(EDGES + 255) / 256, 256>>>(ei);
    gather_kernel<<<(NODES + 7) / 8, 256>>>(x, pos);

    cudaFuncSetAttribute(gin_mma_kernel,
                         cudaFuncAttributeMaxDynamicSharedMemorySize, SM_TOTAL);
    dim3 grid((NODES + 127) / 128, 2);
    gin_mma_kernel<<<grid, 256, SM_TOTAL>>>(
        x, pos, eps, W1, b1, g1, be1, W2, b2, lng, lnb,
        epsp, W1p, b1p, g1p, be1p, W2p, b2p, lnpg, lnpb, out);
}

// round 11
// speedup vs baseline: 1.1786x; 1.1786x over previous
#include <cuda_runtime.h>
#include <cuda_bf16.h>
#include <cstdint>

static constexpr int NODES = 50000;
static constexpr int EDGES = 400000;
static constexpr float LNE = 1e-5f;

__device__ float g_agg[(size_t)NODES * 192];

// ---------------- smem layout (bytes) ----------------
static constexpr int PAR_OFF = 0;                    // 768 floats
static constexpr int RED_OFF = 3072;                 // 256 float2
static constexpr int R1_OFF  = 5120;                 // A-chunk / U region (hi)
static constexpr int R1_HALF = 34816;                // 128*272 (lo at +R1_HALF)
static constexpr int B_OFF   = R1_OFF + 2 * R1_HALF; // 74752: B chunk (hi)
static constexpr int B_HALF  = 17408;                // 64*272 (lo at +B_HALF)
static constexpr int SM_TOTAL = B_OFF + 2 * B_HALF;  // 109568 B -> 2 CTAs/SM
static constexpr int SB = 272;                       // B row stride
static constexpr int SU = 272;                       // U row stride
static constexpr int SA = 144;                       // A chunk row stride (64*2+16)

// ---------------- helpers ----------------
__device__ __forceinline__ uint32_t smem_u32(const void* p) {
    uint32_t a;
    asm("{ .reg .u64 t; cvta.to.shared.u64 t, %1; cvt.u32.u64 %0, t; }" : "=r"(a) : "l"(p));
    return a;
}
__device__ __forceinline__ void split2(float a, float b, uint32_t& hi, uint32_t& lo) {
    __nv_bfloat16 ah = __float2bfloat16_rn(a), bh = __float2bfloat16_rn(b);
    float ar = a - __bfloat162float(ah), br = b - __bfloat162float(bh);
    __nv_bfloat16 al = __float2bfloat16_rn(ar), bl = __float2bfloat16_rn(br);
    hi = (uint32_t)__bfloat16_as_ushort(ah) | ((uint32_t)__bfloat16_as_ushort(bh) << 16);
    lo = (uint32_t)__bfloat16_as_ushort(al) | ((uint32_t)__bfloat16_as_ushort(bl) << 16);
}
__device__ __forceinline__ void ldsm4(uint32_t* r, uint32_t addr) {
    asm volatile("ldmatrix.sync.aligned.m8n8.x4.shared.b16 {%0,%1,%2,%3}, [%4];"
                 : "=r"(r[0]), "=r"(r[1]), "=r"(r[2]), "=r"(r[3]) : "r"(addr));
}
__device__ __forceinline__ void ldsm4t(uint32_t* r, uint32_t addr) {
    asm volatile("ldmatrix.sync.aligned.m8n8.x4.trans.shared.b16 {%0,%1,%2,%3}, [%4];"
                 : "=r"(r[0]), "=r"(r[1]), "=r"(r[2]), "=r"(r[3]) : "r"(addr));
}
__device__ __forceinline__ void mma16816(float* d, const uint32_t* a, const uint32_t* b) {
    asm volatile("mma.sync.aligned.m16n8k16.row.col.f32.bf16.bf16.f32 "
                 "{%0,%1,%2,%3}, {%4,%5,%6,%7}, {%8,%9}, {%0,%1,%2,%3};"
                 : "+f"(d[0]), "+f"(d[1]), "+f"(d[2]), "+f"(d[3])
                 : "r"(a[0]), "r"(a[1]), "r"(a[2]), "r"(a[3]), "r"(b[0]), "r"(b[1]));
}

// 3-pass bf16-split GEMM over ONE 64-k chunk; accumulates into acc.
__device__ __forceinline__ void gemm3c(float acc[2][8][4],
                                       uint32_t aHi, uint32_t aLo, int sa,
                                       uint32_t bHi, uint32_t bLo,
                                       int m0, int n0, int lane)
{
    const uint32_t aoff = (uint32_t)(m0 * sa + (lane & 15) * sa + (lane >> 4) * 16);
    const uint32_t boff = (uint32_t)(n0 * 2 + (lane & 15) * SB + (lane >> 4) * 16);
#pragma unroll 1
    for (int pass = 0; pass < 3; pass++) {
        uint32_t aAddr = ((pass == 2) ? aLo : aHi) + aoff;
        uint32_t bAddr = ((pass == 1) ? bLo : bHi) + boff;
#pragma unroll
        for (int ks = 0; ks < 4; ks++) {
            uint32_t a0[4], a1[4], bf[8][2], r[4];
            ldsm4(a0, aAddr);
            ldsm4(a1, aAddr + 16 * sa);
#pragma unroll
            for (int bt = 0; bt < 4; bt++) {
                ldsm4t(r, bAddr + bt * 32);
                bf[2 * bt][0] = r[0]; bf[2 * bt][1] = r[1];
                bf[2 * bt + 1][0] = r[2]; bf[2 * bt + 1][1] = r[3];
            }
#pragma unroll
            for (int nt = 0; nt < 8; nt++) {
                mma16816(acc[0][nt], a0, bf[nt]);
                mma16816(acc[1][nt], a1, bf[nt]);
            }
            aAddr += 32;       // 16 k-cols * 2B
            bAddr += 16 * SB;  // 16 k-rows
        }
    }
}

// stage 64 rows of W[k0..k0+64)[128] -> B chunk hi/lo
__device__ __forceinline__ void stage_b64(char* smem, const float* __restrict__ W,
                                          int k0, int tid)
{
    for (int idx = tid; idx < 64 * 32; idx += 256) {
        int kl = idx >> 5, c = (idx & 31) * 4;
        float4 w = __ldg((const float4*)(W + (size_t)(k0 + kl) * 128 + c));
        uint32_t h0, l0, h1, l1;
        split2(w.x, w.y, h0, l0);
        split2(w.z, w.w, h1, l1);
        char* p = smem + B_OFF + kl * SB + c * 2;
        *(uint32_t*)p = h0; *(uint32_t*)(p + 4) = h1;
        char* q = p + B_HALF;
        *(uint32_t*)q = l0; *(uint32_t*)(q + 4) = l1;
    }
}

// bias add + LN stats (cross-half via smem); leaves biased values in acc
__device__ __forceinline__ void ln_stats(float acc[2][8][4], char* smem,
                                         const float* s_par, int parOff,
                                         int m0, int n0, int cg, int lane,
                                         float mean[2][2], float rstd[2][2])
{
    float2* s_red = (float2*)(smem + RED_OFF);
    const int grp = lane >> 2, qd = lane & 3;
#pragma unroll
    for (int mt = 0; mt < 2; mt++) {
        float sA = 0.f, qA = 0.f, sB = 0.f, qB = 0.f;
#pragma unroll
        for (int nt = 0; nt < 8; nt++) {
            int n = n0 + nt * 8 + qd * 2;
            float b0v = s_par[parOff + n], b1v = s_par[parOff + n + 1];
            float d0 = acc[mt][nt][0] + b0v, d1 = acc[mt][nt][1] + b1v;
            float d2 = acc[mt][nt][2] + b0v, d3 = acc[mt][nt][3] + b1v;
            acc[mt][nt][0] = d0; acc[mt][nt][1] = d1;
            acc[mt][nt][2] = d2; acc[mt][nt][3] = d3;
            sA += d0 + d1; qA = fmaf(d0, d0, fmaf(d1, d1, qA));
            sB += d2 + d3; qB = fmaf(d2, d2, fmaf(d3, d3, qB));
        }
#pragma unroll
        for (int o = 1; o <= 2; o <<= 1) {
            sA += __shfl_xor_sync(~0u, sA, o); qA += __shfl_xor_sync(~0u, qA, o);
            sB += __shfl_xor_sync(~0u, sB, o); qB += __shfl_xor_sync(~0u, qB, o);
        }
        if (qd == 0) {
            int rA = m0 + mt * 16 + grp;
            s_red[cg * 128 + rA]     = make_float2(sA, qA);
            s_red[cg * 128 + rA + 8] = make_float2(sB, qB);
        }
    }
    __syncthreads();
#pragma unroll
    for (int mt = 0; mt < 2; mt++)
#pragma unroll
        for (int h = 0; h < 2; h++) {
            int r = m0 + mt * 16 + grp + h * 8;
            float2 t0 = s_red[r], t1 = s_red[128 + r];
            float mu = (t0.x + t1.x) * (1.0f / 128.0f);
            float var = fmaf(-mu, mu, (t0.y + t1.y) * (1.0f / 128.0f));
            mean[mt][h] = mu;
            rstd[mt][h] = rsqrtf(var + LNE);
        }
}

// ---------------- aggregation: zero + atomic scatter (R5 proven path) ----------------
__global__ __launch_bounds__(256) void zero_agg_kernel() {
    size_t i = (size_t)blockIdx.x * blockDim.x + threadIdx.x;
    ((float4*)g_agg)[i] = make_float4(0.f, 0.f, 0.f, 0.f);
}

__global__ __launch_bounds__(256) void scatter_kernel(const float* __restrict__ x,
                                                      const float* __restrict__ pos,
                                                      const int* __restrict__ ei) {
    int gw   = blockIdx.x * 8 + (threadIdx.x >> 5);
    int lane = threadIdx.x & 31;
    if (gw >= EDGES) return;
    int src = __ldg(ei + gw);
    int dst = __ldg(ei + EDGES + gw);

    float4 v = __ldg((const float4*)x + (size_t)src * 32 + lane);
    float* a = g_agg + (size_t)dst * 192 + lane * 4;
    asm volatile("red.global.add.v4.f32 [%0], {%1, %2, %3, %4};"
                 :: "l"(a), "f"(v.x), "f"(v.y), "f"(v.z), "f"(v.w) : "memory");
    if (lane < 16) {
        float4 p = __ldg((const float4*)pos + (size_t)src * 16 + lane);
        float* ap = g_agg + (size_t)dst * 192 + 128 + lane * 4;
        asm volatile("red.global.add.v4.f32 [%0], {%1, %2, %3, %4};"
                     :: "l"(ap), "f"(p.x), "f"(p.y), "f"(p.z), "f"(p.w) : "memory");
    }
}

// ---------------- fused HMMA GIN, k-chunked for 2 CTAs/SM ----------------
__global__ __launch_bounds__(256, 2)
void gin_mma_kernel(const float* __restrict__ x, const float* __restrict__ pos,
                    const float* __restrict__ eps,  const float* __restrict__ W1,
                    const float* __restrict__ b1,   const float* __restrict__ g1,
                    const float* __restrict__ be1,  const float* __restrict__ W2,
                    const float* __restrict__ b2,   const float* __restrict__ lng,
                    const float* __restrict__ lnb,
                    const float* __restrict__ epsp, const float* __restrict__ W1p,
                    const float* __restrict__ b1p,  const float* __restrict__ g1p,
                    const float* __restrict__ be1p, const float* __restrict__ W2p,
                    const float* __restrict__ b2p,  const float* __restrict__ lnpg,
                    const float* __restrict__ lnpb,
                    float* __restrict__ out)
{
    extern __shared__ char smem[];
    const uint32_t sbase = smem_u32(smem);
    float* s_par = (float*)smem;
    const int tid = threadIdx.x, lane = tid & 31, wid = tid >> 5;
    const int m0 = (wid & 3) * 32, n0 = (wid >> 2) * 64, cg = wid >> 2;
    const int br = blockIdx.y;
    const int row0 = blockIdx.x * 128;

    const int chunks = br ? 1 : 3;
    const float e1 = 1.0f + __ldg(br ? epsp : eps);
    const float* Wa = br ? W1p : W1;
    const float* Wb = br ? W2p : W2;
    float* outb = out + (br ? (size_t)NODES * 128 : 0);

    // stage LN / bias params
    {
        const float* pars[6] = { br ? b1p : b1, br ? g1p : g1, br ? be1p : be1,
                                 br ? b2p : b2, br ? lnpg : lng, br ? lnpb : lnb };
        for (int j = tid; j < 768; j += 256) s_par[j] = __ldg(pars[j >> 7] + (j & 127));
    }

    float acc[2][8][4];
#pragma unroll
    for (int mt = 0; mt < 2; mt++)
#pragma unroll
        for (int nt = 0; nt < 8; nt++)
#pragma unroll
            for (int c = 0; c < 4; c++) acc[mt][nt][c] = 0.f;

    // ---- GEMM1: k-chunked, A1 = (1+eps)*feat + agg ----
    for (int ch = 0; ch < chunks; ch++) {
        // stage A chunk (128 rows x 64 k-cols, hi/lo)
        for (int idx = tid; idx < 128 * 16; idx += 256) {
            int r = idx >> 4, c = (idx & 15) * 4;
            int gk = ch * 64 + c;
            int row = row0 + r;
            float4 f = make_float4(0.f, 0.f, 0.f, 0.f), a = f;
            if (row < NODES) {
                if (br == 0) {
                    f = (gk < 128) ? __ldg((const float4*)(x + (size_t)row * 128 + gk))
                                   : __ldg((const float4*)(pos + (size_t)row * 64 + (gk - 128)));
                    a = __ldg((const float4*)(g_agg + (size_t)row * 192 + gk));
                } else {
                    f = __ldg((const float4*)(pos + (size_t)row * 64 + gk));
                    a = __ldg((const float4*)(g_agg + (size_t)row * 192 + 128 + gk));
                }
            }
            float v0 = fmaf(e1, f.x, a.x), v1 = fmaf(e1, f.y, a.y);
            float v2 = fmaf(e1, f.z, a.z), v3 = fmaf(e1, f.w, a.w);
            uint32_t h0, l0, h1, l1;
            split2(v0, v1, h0, l0);
            split2(v2, v3, h1, l1);
            char* p = smem + R1_OFF + r * SA + c * 2;
            *(uint32_t*)p = h0; *(uint32_t*)(p + 4) = h1;
            char* q = p + R1_HALF;
            *(uint32_t*)q = l0; *(uint32_t*)(q + 4) = l1;
        }
        stage_b64(smem, Wa, ch * 64, tid);
        __syncthreads();
        gemm3c(acc, sbase + R1_OFF, sbase + R1_OFF + R1_HALF, SA,
               sbase + B_OFF, sbase + B_OFF + B_HALF, m0, n0, lane);
        __syncthreads();
    }

    // ---- epilogue 1: LN + relu -> U (bf16 hi/lo, stride 272, persists) ----
    float mean[2][2], rstd[2][2];
    ln_stats(acc, smem, s_par, 0, m0, n0, cg, lane, mean, rstd);
    {
        const int grp = lane >> 2, qd = lane & 3;
#pragma unroll
        for (int mt = 0; mt < 2; mt++)
#pragma unroll
            for (int h = 0; h < 2; h++) {
                int r = m0 + mt * 16 + grp + h * 8;
                float mu = mean[mt][h], rs = rstd[mt][h];
#pragma unroll
                for (int nt = 0; nt < 8; nt++) {
                    int n = n0 + nt * 8 + qd * 2;
                    int ci = h * 2;
                    float d0 = acc[mt][nt][ci], d1 = acc[mt][nt][ci + 1];
                    float v0 = fmaf((d0 - mu) * rs, s_par[128 + n], s_par[256 + n]);
                    float v1 = fmaf((d1 - mu) * rs, s_par[128 + n + 1], s_par[256 + n + 1]);
                    v0 = fmaxf(v0, 0.f); v1 = fmaxf(v1, 0.f);
                    uint32_t hi, lo;
                    split2(v0, v1, hi, lo);
                    char* p = smem + R1_OFF + r * SU + n * 2;
                    *(uint32_t*)p = hi;
                    *(uint32_t*)(p + R1_HALF) = lo;
                }
            }
    }

    // ---- GEMM2: k-chunked over U (2 chunks of 64) ----
#pragma unroll
    for (int mt = 0; mt < 2; mt++)
#pragma unroll
        for (int nt = 0; nt < 8; nt++)
#pragma unroll
            for (int c = 0; c < 4; c++) acc[mt][nt][c] = 0.f;

    for (int ch = 0; ch < 2; ch++) {
        stage_b64(smem, Wb, ch * 64, tid);
        __syncthreads();   // also covers U writes (ch==0) before first read
        gemm3c(acc, sbase + R1_OFF + ch * 128, sbase + R1_OFF + R1_HALF + ch * 128, SU,
               sbase + B_OFF, sbase + B_OFF + B_HALF, m0, n0, lane);
        __syncthreads();
    }

    // ---- epilogue 2: LN + relu (+ residual) -> out ----
    ln_stats(acc, smem, s_par, 384, m0, n0, cg, lane, mean, rstd);
    {
        const int grp = lane >> 2, qd = lane & 3;
#pragma unroll
        for (int mt = 0; mt < 2; mt++)
#pragma unroll
            for (int h = 0; h < 2; h++) {
                int r = m0 + mt * 16 + grp + h * 8;
                int row = row0 + r;
                if (row >= NODES) continue;
                float mu = mean[mt][h], rs = rstd[mt][h];
#pragma unroll
                for (int nt = 0; nt < 8; nt++) {
                    int n = n0 + nt * 8 + qd * 2;
                    int ci = h * 2;
                    float d0 = acc[mt][nt][ci], d1 = acc[mt][nt][ci + 1];
                    float v0 = fmaf((d0 - mu) * rs, s_par[512 + n], s_par[640 + n]);
                    float v1 = fmaf((d1 - mu) * rs, s_par[512 + n + 1], s_par[640 + n + 1]);
                    v0 = fmaxf(v0, 0.f); v1 = fmaxf(v1, 0.f);
                    if (br == 0) {
                        float2 xv = *(const float2*)(x + (size_t)row * 128 + n);
                        v0 += xv.x; v1 += xv.y;
                    }
                    *(float2*)(outb + (size_t)row * 128 + n) = make_float2(v0, v1);
                }
            }
    }
}

// ---------------- launch ----------------
extern "C" void kernel_launch(void* const* d_in, const int* in_sizes, int n_in,
                              void* d_out, int out_size) {
    const float* x    = (const float*)d_in[0];
    const float* pos  = (const float*)d_in[1];
    const int*   ei   = (const int*)d_in[2];
    const float* eps  = (const float*)d_in[3];
    const float* W1   = (const float*)d_in[4];
    const float* b1   = (const float*)d_in[5];
    const float* g1   = (const float*)d_in[6];
    const float* be1  = (const float*)d_in[7];
    const float* W2   = (const float*)d_in[8];
    const float* b2   = (const float*)d_in[9];
    const float* lng  = (const float*)d_in[10];
    const float* lnb  = (const float*)d_in[11];
    const float* epsp = (const float*)d_in[12];
    const float* W1p  = (const float*)d_in[13];
    const float* b1p  = (const float*)d_in[14];
    const float* g1p  = (const float*)d_in[15];
    const float* be1p = (const float*)d_in[16];
    const float* W2p  = (const float*)d_in[17];
    const float* b2p  = (const float*)d_in[18];
    const float* lnpg = (const float*)d_in[19];
    const float* lnpb = (const float*)d_in[20];
    float* out = (float*)d_out;

    zero_agg_kernel<<<(NODES * 192 / 4) / 256, 256>>>();
    scatter_kernel<<<EDGES / 8, 256>>>(x, pos, ei);

    cudaFuncSetAttribute(gin_mma_kernel,
                         cudaFuncAttributeMaxDynamicSharedMemorySize, SM_TOTAL);
    dim3 grid((NODES + 127) / 128, 2);
    gin_mma_kernel<<<grid, 256, SM_TOTAL>>>(
        x, pos, eps, W1, b1, g1, be1, W2, b2, lng, lnb,
        epsp, W1p, b1p, g1p, be1p, W2p, b2p, lnpg, lnpb, out);
}

// round 12
// speedup vs baseline: 1.2282x; 1.0421x over previous
#include <cuda_runtime.h>
#include <cuda_bf16.h>
#include <cstdint>

static constexpr int NODES = 50000;
static constexpr int EDGES = 400000;
static constexpr float LNE = 1e-5f;

__device__ float g_agg[(size_t)NODES * 192];

// ---------------- smem layout (bytes) ----------------
static constexpr int PAR_OFF = 0;               // 768 floats (b1,g1,be1,b2,g2,be2)
static constexpr int RED_OFF = 3072;            // 256 float2 (LN partial sums)
static constexpr int AH_OFF  = 5120;            // A hi (max 128 x 400B)
static constexpr int AL_OFF  = AH_OFF + 51200;  // A lo
static constexpr int BH_OFF  = AL_OFF + 51200;  // B hi (max 192 x 272B)
static constexpr int BL_OFF  = BH_OFF + 52224;  // B lo
static constexpr int SM_TOTAL = BL_OFF + 52224; // 211968 B
static constexpr int SB = 272;                  // B row stride (128*2 + 16)
static constexpr int SU = 272;                  // U row stride

// ---------------- helpers ----------------
__device__ __forceinline__ uint32_t smem_u32(const void* p) {
    uint32_t a;
    asm("{ .reg .u64 t; cvta.to.shared.u64 t, %1; cvt.u32.u64 %0, t; }" : "=r"(a) : "l"(p));
    return a;
}
__device__ __forceinline__ void split2(float a, float b, uint32_t& hi, uint32_t& lo) {
    __nv_bfloat16 ah = __float2bfloat16_rn(a), bh = __float2bfloat16_rn(b);
    float ar = a - __bfloat162float(ah), br = b - __bfloat162float(bh);
    __nv_bfloat16 al = __float2bfloat16_rn(ar), bl = __float2bfloat16_rn(br);
    hi = (uint32_t)__bfloat16_as_ushort(ah) | ((uint32_t)__bfloat16_as_ushort(bh) << 16);
    lo = (uint32_t)__bfloat16_as_ushort(al) | ((uint32_t)__bfloat16_as_ushort(bl) << 16);
}
__device__ __forceinline__ void ldsm4(uint32_t* r, uint32_t addr) {
    asm volatile("ldmatrix.sync.aligned.m8n8.x4.shared.b16 {%0,%1,%2,%3}, [%4];"
                 : "=r"(r[0]), "=r"(r[1]), "=r"(r[2]), "=r"(r[3]) : "r"(addr));
}
__device__ __forceinline__ void ldsm4t(uint32_t* r, uint32_t addr) {
    asm volatile("ldmatrix.sync.aligned.m8n8.x4.trans.shared.b16 {%0,%1,%2,%3}, [%4];"
                 : "=r"(r[0]), "=r"(r[1]), "=r"(r[2]), "=r"(r[3]) : "r"(addr));
}
__device__ __forceinline__ void mma16816(float* d, const uint32_t* a, const uint32_t* b) {
    asm volatile("mma.sync.aligned.m16n8k16.row.col.f32.bf16.bf16.f32 "
                 "{%0,%1,%2,%3}, {%4,%5,%6,%7}, {%8,%9}, {%0,%1,%2,%3};"
                 : "+f"(d[0]), "+f"(d[1]), "+f"(d[2]), "+f"(d[3])
                 : "r"(a[0]), "r"(a[1]), "r"(a[2]), "r"(a[3]), "r"(b[0]), "r"(b[1]));
}

// Fused 3-term bf16-split GEMM: D += Ah*Bh + Al*Bh + Ah*Bl, single k-loop.
// Per k-step: 4 A-ldsm + 8 B-ldsm (vs 18 in the 3-pass version), 48 MMAs.
__device__ __forceinline__ void gemm3(float acc[2][8][4], uint32_t sbase,
                                      int sa, int ksteps, int m0, int n0, int lane)
{
    uint32_t aHi = sbase + AH_OFF + (uint32_t)(m0 * sa + (lane & 15) * sa + (lane >> 4) * 16);
    uint32_t aLo = aHi + (AL_OFF - AH_OFF);
    uint32_t bHi = sbase + BH_OFF + (uint32_t)(n0 * 2 + (lane & 15) * SB + (lane >> 4) * 16);
    uint32_t bLo = bHi + (BL_OFF - BH_OFF);

    for (int ks = 0; ks < ksteps; ks++) {
        uint32_t ah0[4], ah1[4], al0[4], al1[4];
        ldsm4(ah0, aHi);
        ldsm4(ah1, aHi + 16 * sa);
        ldsm4(al0, aLo);
        ldsm4(al1, aLo + 16 * sa);
#pragma unroll
        for (int bt = 0; bt < 4; bt++) {
            uint32_t rh[4], rl[4];
            ldsm4t(rh, bHi + bt * 32);
            ldsm4t(rl, bLo + bt * 32);
            const int n0t = 2 * bt, n1t = 2 * bt + 1;
            // hi*hi
            mma16816(acc[0][n0t], ah0, rh);
            mma16816(acc[1][n0t], ah1, rh);
            mma16816(acc[0][n1t], ah0, rh + 2);
            mma16816(acc[1][n1t], ah1, rh + 2);
            // lo*hi
            mma16816(acc[0][n0t], al0, rh);
            mma16816(acc[1][n0t], al1, rh);
            mma16816(acc[0][n1t], al0, rh + 2);
            mma16816(acc[1][n1t], al1, rh + 2);
            // hi*lo
            mma16816(acc[0][n0t], ah0, rl);
            mma16816(acc[1][n0t], ah1, rl);
            mma16816(acc[0][n1t], ah0, rl + 2);
            mma16816(acc[1][n1t], ah1, rl + 2);
        }
        aHi += 32;  aLo += 32;        // 16 k-cols * 2B
        bHi += 16 * SB;  bLo += 16 * SB;  // 16 k-rows
    }
}

// stage weights W[rows][128] -> B hi/lo smem
__device__ __forceinline__ void stage_w(char* smem, const float* __restrict__ W,
                                        int rows, int tid)
{
    for (int idx = tid; idx < rows * 32; idx += 256) {
        int k = idx >> 5, c = (idx & 31) * 4;
        float4 w = __ldg((const float4*)(W + (size_t)k * 128 + c));
        uint32_t h0, l0, h1, l1;
        split2(w.x, w.y, h0, l0);
        split2(w.z, w.w, h1, l1);
        char* p = smem + BH_OFF + k * SB + c * 2;
        *(uint32_t*)p = h0; *(uint32_t*)(p + 4) = h1;
        char* q = p + (BL_OFF - BH_OFF);
        *(uint32_t*)q = l0; *(uint32_t*)(q + 4) = l1;
    }
}

// bias add + LN stats (cross-half via smem); leaves biased values in acc
__device__ __forceinline__ void ln_stats(float acc[2][8][4], char* smem,
                                         const float* s_par, int parOff,
                                         int m0, int n0, int cg, int lane,
                                         float mean[2][2], float rstd[2][2])
{
    float2* s_red = (float2*)(smem + RED_OFF);
    const int grp = lane >> 2, qd = lane & 3;
#pragma unroll
    for (int mt = 0; mt < 2; mt++) {
        float sA = 0.f, qA = 0.f, sB = 0.f, qB = 0.f;
#pragma unroll
        for (int nt = 0; nt < 8; nt++) {
            int n = n0 + nt * 8 + qd * 2;
            float b0v = s_par[parOff + n], b1v = s_par[parOff + n + 1];
            float d0 = acc[mt][nt][0] + b0v, d1 = acc[mt][nt][1] + b1v;
            float d2 = acc[mt][nt][2] + b0v, d3 = acc[mt][nt][3] + b1v;
            acc[mt][nt][0] = d0; acc[mt][nt][1] = d1;
            acc[mt][nt][2] = d2; acc[mt][nt][3] = d3;
            sA += d0 + d1; qA = fmaf(d0, d0, fmaf(d1, d1, qA));
            sB += d2 + d3; qB = fmaf(d2, d2, fmaf(d3, d3, qB));
        }
#pragma unroll
        for (int o = 1; o <= 2; o <<= 1) {
            sA += __shfl_xor_sync(~0u, sA, o); qA += __shfl_xor_sync(~0u, qA, o);
            sB += __shfl_xor_sync(~0u, sB, o); qB += __shfl_xor_sync(~0u, qB, o);
        }
        if (qd == 0) {
            int rA = m0 + mt * 16 + grp;
            s_red[cg * 128 + rA]     = make_float2(sA, qA);
            s_red[cg * 128 + rA + 8] = make_float2(sB, qB);
        }
    }
    __syncthreads();
#pragma unroll
    for (int mt = 0; mt < 2; mt++)
#pragma unroll
        for (int h = 0; h < 2; h++) {
            int r = m0 + mt * 16 + grp + h * 8;
            float2 t0 = s_red[r], t1 = s_red[128 + r];
            float mu = (t0.x + t1.x) * (1.0f / 128.0f);
            float var = fmaf(-mu, mu, (t0.y + t1.y) * (1.0f / 128.0f));
            mean[mt][h] = mu;
            rstd[mt][h] = rsqrtf(var + LNE);
        }
}

// ---------------- aux kernels ----------------
__global__ __launch_bounds__(256) void zero_agg_kernel() {
    size_t i = (size_t)blockIdx.x * blockDim.x + threadIdx.x;
    ((float4*)g_agg)[i] = make_float4(0.f, 0.f, 0.f, 0.f);
}

__global__ __launch_bounds__(256) void scatter_kernel(const float* __restrict__ x,
                                                      const float* __restrict__ pos,
                                                      const int* __restrict__ ei) {
    int gw   = blockIdx.x * 8 + (threadIdx.x >> 5);
    int lane = threadIdx.x & 31;
    if (gw >= EDGES) return;
    int src = __ldg(ei + gw);
    int dst = __ldg(ei + EDGES + gw);

    float4 v = __ldg((const float4*)x + (size_t)src * 32 + lane);
    float* a = g_agg + (size_t)dst * 192 + lane * 4;
    asm volatile("red.global.add.v4.f32 [%0], {%1, %2, %3, %4};"
                 :: "l"(a), "f"(v.x), "f"(v.y), "f"(v.z), "f"(v.w) : "memory");
    if (lane < 16) {
        float4 p = __ldg((const float4*)pos + (size_t)src * 16 + lane);
        float* ap = g_agg + (size_t)dst * 192 + 128 + lane * 4;
        asm volatile("red.global.add.v4.f32 [%0], {%1, %2, %3, %4};"
                     :: "l"(ap), "f"(p.x), "f"(p.y), "f"(p.z), "f"(p.w) : "memory");
    }
}

// ---------------- fused HMMA GIN (both branches via blockIdx.y) ----------------
__global__ __launch_bounds__(256, 1)
void gin_mma_kernel(const float* __restrict__ x, const float* __restrict__ pos,
                    const float* __restrict__ eps,  const float* __restrict__ W1,
                    const float* __restrict__ b1,   const float* __restrict__ g1,
                    const float* __restrict__ be1,  const float* __restrict__ W2,
                    const float* __restrict__ b2,   const float* __restrict__ lng,
                    const float* __restrict__ lnb,
                    const float* __restrict__ epsp, const float* __restrict__ W1p,
                    const float* __restrict__ b1p,  const float* __restrict__ g1p,
                    const float* __restrict__ be1p, const float* __restrict__ W2p,
                    const float* __restrict__ b2p,  const float* __restrict__ lnpg,
                    const float* __restrict__ lnpb,
                    float* __restrict__ out)
{
    extern __shared__ char smem[];
    const uint32_t sbase = smem_u32(smem);
    float* s_par = (float*)smem;
    const int tid = threadIdx.x, lane = tid & 31, wid = tid >> 5;
    const int m0 = (wid & 3) * 32, n0 = (wid >> 2) * 64, cg = wid >> 2;
    const int br = blockIdx.y;
    const int row0 = blockIdx.x * 128;

    const int din = br ? 64 : 192;
    const int sa1 = br ? 144 : 400;   // A row stride (din*2 + 16)
    const int ks1 = br ? 4 : 12;
    const float e1 = 1.0f + __ldg(br ? epsp : eps);
    const float* Wa = br ? W1p : W1;
    const float* Wb = br ? W2p : W2;
    float* outb = out + (br ? (size_t)NODES * 128 : 0);

    // stage LN / bias params
    {
        const float* pars[6] = { br ? b1p : b1, br ? g1p : g1, br ? be1p : be1,
                                 br ? b2p : b2, br ? lnpg : lng, br ? lnpb : lnb };
        for (int j = tid; j < 768; j += 256) s_par[j] = __ldg(pars[j >> 7] + (j & 127));
    }

    // stage A1 = (1+eps)*feat + agg   (bf16 hi/lo)
    {
        const int nf4 = din / 4;
        for (int idx = tid; idx < 128 * nf4; idx += 256) {
            int r = idx / nf4, c = (idx - r * nf4) * 4;
            int row = row0 + r;
            float4 f = make_float4(0.f, 0.f, 0.f, 0.f), a = f;
            if (row < NODES) {
                if (br == 0) {
                    f = (c < 128) ? __ldg((const float4*)(x + (size_t)row * 128 + c))
                                  : __ldg((const float4*)(pos + (size_t)row * 64 + (c - 128)));
                    a = __ldg((const float4*)(g_agg + (size_t)row * 192 + c));
                } else {
                    f = __ldg((const float4*)(pos + (size_t)row * 64 + c));
                    a = __ldg((const float4*)(g_agg + (size_t)row * 192 + 128 + c));
                }
            }
            float v0 = fmaf(e1, f.x, a.x), v1 = fmaf(e1, f.y, a.y);
            float v2 = fmaf(e1, f.z, a.z), v3 = fmaf(e1, f.w, a.w);
            uint32_t h0, l0, h1, l1;
            split2(v0, v1, h0, l0);
            split2(v2, v3, h1, l1);
            char* p = smem + AH_OFF + r * sa1 + c * 2;
            *(uint32_t*)p = h0; *(uint32_t*)(p + 4) = h1;
            char* q = p + (AL_OFF - AH_OFF);
            *(uint32_t*)q = l0; *(uint32_t*)(q + 4) = l1;
        }
    }
    stage_w(smem, Wa, din, tid);
    __syncthreads();

    // ---- GEMM1 ----
    float acc[2][8][4];
#pragma unroll
    for (int mt = 0; mt < 2; mt++)
#pragma unroll
        for (int nt = 0; nt < 8; nt++)
#pragma unroll
            for (int c = 0; c < 4; c++) acc[mt][nt][c] = 0.f;

    gemm3(acc, sbase, sa1, ks1, m0, n0, lane);
    __syncthreads();   // A/B regions free for reuse

    // ---- epilogue 1: LN + relu -> U (bf16 hi/lo in A region, stride 272) ----
    float mean[2][2], rstd[2][2];
    ln_stats(acc, smem, s_par, 0, m0, n0, cg, lane, mean, rstd);
    {
        const int grp = lane >> 2, qd = lane & 3;
#pragma unroll
        for (int mt = 0; mt < 2; mt++)
#pragma unroll
            for (int h = 0; h < 2; h++) {
                int r = m0 + mt * 16 + grp + h * 8;
                float mu = mean[mt][h], rs = rstd[mt][h];
#pragma unroll
                for (int nt = 0; nt < 8; nt++) {
                    int n = n0 + nt * 8 + qd * 2;
                    int ci = h * 2;
                    float d0 = acc[mt][nt][ci], d1 = acc[mt][nt][ci + 1];
                    float v0 = fmaf((d0 - mu) * rs, s_par[128 + n], s_par[256 + n]);
                    float v1 = fmaf((d1 - mu) * rs, s_par[128 + n + 1], s_par[256 + n + 1]);
                    v0 = fmaxf(v0, 0.f); v1 = fmaxf(v1, 0.f);
                    uint32_t hi, lo;
                    split2(v0, v1, hi, lo);
                    char* p = smem + AH_OFF + r * SU + n * 2;
                    *(uint32_t*)p = hi;
                    *(uint32_t*)(p + (AL_OFF - AH_OFF)) = lo;
                }
            }
    }
    stage_w(smem, Wb, 128, tid);
    __syncthreads();

    // ---- GEMM2 ----
#pragma unroll
    for (int mt = 0; mt < 2; mt++)
#pragma unroll
        for (int nt = 0; nt < 8; nt++)
#pragma unroll
            for (int c = 0; c < 4; c++) acc[mt][nt][c] = 0.f;

    gemm3(acc, sbase, SU, 8, m0, n0, lane);

    // ---- epilogue 2: LN + relu (+ residual) -> out ----
    ln_stats(acc, smem, s_par, 384, m0, n0, cg, lane, mean, rstd);
    {
        const int grp = lane >> 2, qd = lane & 3;
#pragma unroll
        for (int mt = 0; mt < 2; mt++)
#pragma unroll
            for (int h = 0; h < 2; h++) {
                int r = m0 + mt * 16 + grp + h * 8;
                int row = row0 + r;
                if (row >= NODES) continue;
                float mu = mean[mt][h], rs = rstd[mt][h];
#pragma unroll
                for (int nt = 0; nt < 8; nt++) {
                    int n = n0 + nt * 8 + qd * 2;
                    int ci = h * 2;
                    float d0 = acc[mt][nt][ci], d1 = acc[mt][nt][ci + 1];
                    float v0 = fmaf((d0 - mu) * rs, s_par[512 + n], s_par[640 + n]);
                    float v1 = fmaf((d1 - mu) * rs, s_par[512 + n + 1], s_par[640 + n + 1]);
                    v0 = fmaxf(v0, 0.f); v1 = fmaxf(v1, 0.f);
                    if (br == 0) {
                        float2 xv = *(const float2*)(x + (size_t)row * 128 + n);
                        v0 += xv.x; v1 += xv.y;
                    }
                    *(float2*)(outb + (size_t)row * 128 + n) = make_float2(v0, v1);
                }
            }
    }
}

// ---------------- launch ----------------
extern "C" void kernel_launch(void* const* d_in, const int* in_sizes, int n_in,
                              void* d_out, int out_size) {
    const float* x    = (const float*)d_in[0];
    const float* pos  = (const float*)d_in[1];
    const int*   ei   = (const int*)d_in[2];
    const float* eps  = (const float*)d_in[3];
    const float* W1   = (const float*)d_in[4];
    const float* b1   = (const float*)d_in[5];
    const float* g1   = (const float*)d_in[6];
    const float* be1  = (const float*)d_in[7];
    const float* W2   = (const float*)d_in[8];
    const float* b2   = (const float*)d_in[9];
    const float* lng  = (const float*)d_in[10];
    const float* lnb  = (const float*)d_in[11];
    const float* epsp = (const float*)d_in[12];
    const float* W1p  = (const float*)d_in[13];
    const float* b1p  = (const float*)d_in[14];
    const float* g1p  = (const float*)d_in[15];
    const float* be1p = (const float*)d_in[16];
    const float* W2p  = (const float*)d_in[17];
    const float* b2p  = (const float*)d_in[18];
    const float* lnpg = (const float*)d_in[19];
    const float* lnpb = (const float*)d_in[20];
    float* out = (float*)d_out;

    zero_agg_kernel<<<(NODES * 192 / 4) / 256, 256>>>();
    scatter_kernel<<<EDGES / 8, 256>>>(x, pos, ei);

    cudaFuncSetAttribute(gin_mma_kernel,
                         cudaFuncAttributeMaxDynamicSharedMemorySize, SM_TOTAL);
    dim3 grid((NODES + 127) / 128, 2);
    gin_mma_kernel<<<grid, 256, SM_TOTAL>>>(
        x, pos, eps, W1, b1, g1, be1, W2, b2, lng, lnb,
        epsp, W1p, b1p, g1p, be1p, W2p, b2p, lnpg, lnpb, out);
}

// round 17
// speedup vs baseline: 1.3569x; 1.1048x over previous
#include <cuda_runtime.h>
#include <cuda_fp16.h>
#include <cstdint>

static constexpr int NODES = 50000;
static constexpr int EDGES = 400000;
static constexpr float LNE = 1e-5f;

__device__ float g_agg[(size_t)NODES * 192];

// ---------------- smem layout (bytes) ----------------
static constexpr int PAR_OFF = 0;               // 768 floats (b1,g1,be1,b2,g2,be2)
static constexpr int RED_OFF = 3072;            // 256 float2 (LN partial sums)
static constexpr int AH_OFF  = 5120;            // A hi fp16 (max 128 x 400B)
static constexpr int AL_OFF  = AH_OFF + 51200;  // A lo fp16
static constexpr int BH_OFF  = AL_OFF + 51200;  // B fp16 (max 192 x 272B)
static constexpr int SM_TOTAL = BH_OFF + 52224; // 159744 B
static constexpr int SB = 272;                  // B row stride (128*2 + 16)
static constexpr int SU = 272;                  // U row stride

// ---------------- helpers ----------------
__device__ __forceinline__ uint32_t smem_u32(const void* p) {
    uint32_t a;
    asm("{ .reg .u64 t; cvta.to.shared.u64 t, %1; cvt.u32.u64 %0, t; }" : "=r"(a) : "l"(p));
    return a;
}
// 2-term fp16 split of two floats: hi = (h(a),h(b)), lo = residuals
__device__ __forceinline__ void splitf2(float a, float b, uint32_t& hi, uint32_t& lo) {
    __half ah = __float2half_rn(a), bh = __float2half_rn(b);
    float ar = a - __half2float(ah), br = b - __half2float(bh);
    __half al = __float2half_rn(ar), bl = __float2half_rn(br);
    hi = (uint32_t)__half_as_ushort(ah) | ((uint32_t)__half_as_ushort(bh) << 16);
    lo = (uint32_t)__half_as_ushort(al) | ((uint32_t)__half_as_ushort(bl) << 16);
}
__device__ __forceinline__ uint32_t pack_h2(float a, float b) {
    __half2 p = __floats2half2_rn(a, b);
    return *(uint32_t*)&p;
}
__device__ __forceinline__ void ldsm4(uint32_t* r, uint32_t addr) {
    asm volatile("ldmatrix.sync.aligned.m8n8.x4.shared.b16 {%0,%1,%2,%3}, [%4];"
                 : "=r"(r[0]), "=r"(r[1]), "=r"(r[2]), "=r"(r[3]) : "r"(addr));
}
__device__ __forceinline__ void ldsm4t(uint32_t* r, uint32_t addr) {
    asm volatile("ldmatrix.sync.aligned.m8n8.x4.trans.shared.b16 {%0,%1,%2,%3}, [%4];"
                 : "=r"(r[0]), "=r"(r[1]), "=r"(r[2]), "=r"(r[3]) : "r"(addr));
}
__device__ __forceinline__ void mma16816(float* d, const uint32_t* a, const uint32_t* b) {
    asm volatile("mma.sync.aligned.m16n8k16.row.col.f32.f16.f16.f32 "
                 "{%0,%1,%2,%3}, {%4,%5,%6,%7}, {%8,%9}, {%0,%1,%2,%3};"
                 : "+f"(d[0]), "+f"(d[1]), "+f"(d[2]), "+f"(d[3])
                 : "r"(a[0]), "r"(a[1]), "r"(a[2]), "r"(a[3]), "r"(b[0]), "r"(b[1]));
}

// Fused 2-term fp16-split GEMM: D += Ah*B + Al*B, single k-loop.
// Per k-step: 4 A-ldsm + 4 B-ldsm, 32 MMAs.
__device__ __forceinline__ void gemm2t(float acc[2][8][4], uint32_t sbase,
                                       int sa, int ksteps, int m0, int n0, int lane)
{
    uint32_t aHi = sbase + AH_OFF + (uint32_t)(m0 * sa + (lane & 15) * sa + (lane >> 4) * 16);
    uint32_t aLo = aHi + (AL_OFF - AH_OFF);
    uint32_t bH  = sbase + BH_OFF + (uint32_t)(n0 * 2 + (lane & 15) * SB + (lane >> 4) * 16);

    for (int ks = 0; ks < ksteps; ks++) {
        uint32_t ah0[4], ah1[4], al0[4], al1[4];
        ldsm4(ah0, aHi);
        ldsm4(ah1, aHi + 16 * sa);
        ldsm4(al0, aLo);
        ldsm4(al1, aLo + 16 * sa);
#pragma unroll
        for (int bt = 0; bt < 4; bt++) {
            uint32_t rh[4];
            ldsm4t(rh, bH + bt * 32);
            const int n0t = 2 * bt, n1t = 2 * bt + 1;
            mma16816(acc[0][n0t], ah0, rh);
            mma16816(acc[1][n0t], ah1, rh);
            mma16816(acc[0][n1t], ah0, rh + 2);
            mma16816(acc[1][n1t], ah1, rh + 2);
            mma16816(acc[0][n0t], al0, rh);
            mma16816(acc[1][n0t], al1, rh);
            mma16816(acc[0][n1t], al0, rh + 2);
            mma16816(acc[1][n1t], al1, rh + 2);
        }
        aHi += 32;  aLo += 32;   // 16 k-cols * 2B
        bH += 16 * SB;           // 16 k-rows
    }
}

// stage weights W[rows][128] -> B fp16 smem (single term)
__device__ __forceinline__ void stage_w(char* smem, const float* __restrict__ W,
                                        int rows, int tid)
{
    for (int idx = tid; idx < rows * 32; idx += 256) {
        int k = idx >> 5, c = (idx & 31) * 4;
        float4 w = __ldg((const float4*)(W + (size_t)k * 128 + c));
        char* p = smem + BH_OFF + k * SB + c * 2;
        *(uint32_t*)p = pack_h2(w.x, w.y);
        *(uint32_t*)(p + 4) = pack_h2(w.z, w.w);
    }
}

// bias add + LN stats (cross-half via smem); leaves biased values in acc
__device__ __forceinline__ void ln_stats(float acc[2][8][4], char* smem,
                                         const float* s_par, int parOff,
                                         int m0, int n0, int cg, int lane,
                                         float mean[2][2], float rstd[2][2])
{
    float2* s_red = (float2*)(smem + RED_OFF);
    const int grp = lane >> 2, qd = lane & 3;
#pragma unroll
    for (int mt = 0; mt < 2; mt++) {
        float sA = 0.f, qA = 0.f, sB = 0.f, qB = 0.f;
#pragma unroll
        for (int nt = 0; nt < 8; nt++) {
            int n = n0 + nt * 8 + qd * 2;
            float b0v = s_par[parOff + n], b1v = s_par[parOff + n + 1];
            float d0 = acc[mt][nt][0] + b0v, d1 = acc[mt][nt][1] + b1v;
            float d2 = acc[mt][nt][2] + b0v, d3 = acc[mt][nt][3] + b1v;
            acc[mt][nt][0] = d0; acc[mt][nt][1] = d1;
            acc[mt][nt][2] = d2; acc[mt][nt][3] = d3;
            sA += d0 + d1; qA = fmaf(d0, d0, fmaf(d1, d1, qA));
            sB += d2 + d3; qB = fmaf(d2, d2, fmaf(d3, d3, qB));
        }
#pragma unroll
        for (int o = 1; o <= 2; o <<= 1) {
            sA += __shfl_xor_sync(~0u, sA, o); qA += __shfl_xor_sync(~0u, qA, o);
            sB += __shfl_xor_sync(~0u, sB, o); qB += __shfl_xor_sync(~0u, qB, o);
        }
        if (qd == 0) {
            int rA = m0 + mt * 16 + grp;
            s_red[cg * 128 + rA]     = make_float2(sA, qA);
            s_red[cg * 128 + rA + 8] = make_float2(sB, qB);
        }
    }
    __syncthreads();
#pragma unroll
    for (int mt = 0; mt < 2; mt++)
#pragma unroll
        for (int h = 0; h < 2; h++) {
            int r = m0 + mt * 16 + grp + h * 8;
            float2 t0 = s_red[r], t1 = s_red[128 + r];
            float mu = (t0.x + t1.x) * (1.0f / 128.0f);
            float var = fmaf(-mu, mu, (t0.y + t1.y) * (1.0f / 128.0f));
            mean[mt][h] = mu;
            rstd[mt][h] = rsqrtf(var + LNE);
        }
}

// ---------------- aux kernels ----------------
__global__ __launch_bounds__(256) void zero_agg_kernel() {
    size_t i = (size_t)blockIdx.x * blockDim.x + threadIdx.x;
    ((float4*)g_agg)[i] = make_float4(0.f, 0.f, 0.f, 0.f);
}

__global__ __launch_bounds__(256) void scatter_kernel(const float* __restrict__ x,
                                                      const float* __restrict__ pos,
                                                      const int* __restrict__ ei) {
    int gw   = blockIdx.x * 8 + (threadIdx.x >> 5);
    int lane = threadIdx.x & 31;
    if (gw >= EDGES) return;
    int src = __ldg(ei + gw);
    int dst = __ldg(ei + EDGES + gw);

    float4 v = __ldg((const float4*)x + (size_t)src * 32 + lane);
    float* a = g_agg + (size_t)dst * 192 + lane * 4;
    asm volatile("red.global.add.v4.f32 [%0], {%1, %2, %3, %4};"
                 :: "l"(a), "f"(v.x), "f"(v.y), "f"(v.z), "f"(v.w) : "memory");
    if (lane < 16) {
        float4 p = __ldg((const float4*)pos + (size_t)src * 16 + lane);
        float* ap = g_agg + (size_t)dst * 192 + 128 + lane * 4;
        asm volatile("red.global.add.v4.f32 [%0], {%1, %2, %3, %4};"
                     :: "l"(ap), "f"(p.x), "f"(p.y), "f"(p.z), "f"(p.w) : "memory");
    }
}

// ---------------- fused HMMA GIN (both branches via blockIdx.y) ----------------
__global__ __launch_bounds__(256, 1)
void gin_mma_kernel(const float* __restrict__ x, const float* __restrict__ pos,
                    const float* __restrict__ eps,  const float* __restrict__ W1,
                    const float* __restrict__ b1,   const float* __restrict__ g1,
                    const float* __restrict__ be1,  const float* __restrict__ W2,
                    const float* __restrict__ b2,   const float* __restrict__ lng,
                    const float* __restrict__ lnb,
                    const float* __restrict__ epsp, const float* __restrict__ W1p,
                    const float* __restrict__ b1p,  const float* __restrict__ g1p,
                    const float* __restrict__ be1p, const float* __restrict__ W2p,
                    const float* __restrict__ b2p,  const float* __restrict__ lnpg,
                    const float* __restrict__ lnpb,
                    float* __restrict__ out)
{
    extern __shared__ char smem[];
    const uint32_t sbase = smem_u32(smem);
    float* s_par = (float*)smem;
    const int tid = threadIdx.x, lane = tid & 31, wid = tid >> 5;
    const int m0 = (wid & 3) * 32, n0 = (wid >> 2) * 64, cg = wid >> 2;
    const int br = blockIdx.y;
    const int row0 = blockIdx.x * 128;

    const int din = br ? 64 : 192;
    const int sa1 = br ? 144 : 400;   // A row stride (din*2 + 16)
    const int ks1 = br ? 4 : 12;
    const float e1 = 1.0f + __ldg(br ? epsp : eps);
    const float* Wa = br ? W1p : W1;
    const float* Wb = br ? W2p : W2;
    float* outb = out + (br ? (size_t)NODES * 128 : 0);

    // stage LN / bias params
    {
        const float* pars[6] = { br ? b1p : b1, br ? g1p : g1, br ? be1p : be1,
                                 br ? b2p : b2, br ? lnpg : lng, br ? lnpb : lnb };
        for (int j = tid; j < 768; j += 256) s_par[j] = __ldg(pars[j >> 7] + (j & 127));
    }

    // stage A1 = (1+eps)*feat + agg   (fp16 hi/lo)
    {
        const int nf4 = din / 4;
        for (int idx = tid; idx < 128 * nf4; idx += 256) {
            int r = idx / nf4, c = (idx - r * nf4) * 4;
            int row = row0 + r;
            float4 f = make_float4(0.f, 0.f, 0.f, 0.f), a = f;
            if (row < NODES) {
                if (br == 0) {
                    f = (c < 128) ? __ldg((const float4*)(x + (size_t)row * 128 + c))
                                  : __ldg((const float4*)(pos + (size_t)row * 64 + (c - 128)));
                    a = __ldg((const float4*)(g_agg + (size_t)row * 192 + c));
                } else {
                    f = __ldg((const float4*)(pos + (size_t)row * 64 + c));
                    a = __ldg((const float4*)(g_agg + (size_t)row * 192 + 128 + c));
                }
            }
            float v0 = fmaf(e1, f.x, a.x), v1 = fmaf(e1, f.y, a.y);
            float v2 = fmaf(e1, f.z, a.z), v3 = fmaf(e1, f.w, a.w);
            uint32_t h0, l0, h1, l1;
            splitf2(v0, v1, h0, l0);
            splitf2(v2, v3, h1, l1);
            char* p = smem + AH_OFF + r * sa1 + c * 2;
            *(uint32_t*)p = h0; *(uint32_t*)(p + 4) = h1;
            char* q = p + (AL_OFF - AH_OFF);
            *(uint32_t*)q = l0; *(uint32_t*)(q + 4) = l1;
        }
    }
    stage_w(smem, Wa, din, tid);
    __syncthreads();

    // ---- GEMM1 ----
    float acc[2][8][4];
#pragma unroll
    for (int mt = 0; mt < 2; mt++)
#pragma unroll
        for (int nt = 0; nt < 8; nt++)
#pragma unroll
            for (int c = 0; c < 4; c++) acc[mt][nt][c] = 0.f;

    gemm2t(acc, sbase, sa1, ks1, m0, n0, lane);
    __syncthreads();   // A/B regions free for reuse

    // ---- epilogue 1: LN + relu -> U (fp16 hi/lo in A region, stride 272) ----
    float mean[2][2], rstd[2][2];
    ln_stats(acc, smem, s_par, 0, m0, n0, cg, lane, mean, rstd);
    {
        const int grp = lane >> 2, qd = lane & 3;
#pragma unroll
        for (int mt = 0; mt < 2; mt++)
#pragma unroll
            for (int h = 0; h < 2; h++) {
                int r = m0 + mt * 16 + grp + h * 8;
                float mu = mean[mt][h], rs = rstd[mt][h];
#pragma unroll
                for (int nt = 0; nt < 8; nt++) {
                    int n = n0 + nt * 8 + qd * 2;
                    int ci = h * 2;
                    float d0 = acc[mt][nt][ci], d1 = acc[mt][nt][ci + 1];
                    float v0 = fmaf((d0 - mu) * rs, s_par[128 + n], s_par[256 + n]);
                    float v1 = fmaf((d1 - mu) * rs, s_par[128 + n + 1], s_par[256 + n + 1]);
                    v0 = fmaxf(v0, 0.f); v1 = fmaxf(v1, 0.f);
                    uint32_t hi, lo;
                    splitf2(v0, v1, hi, lo);
                    char* p = smem + AH_OFF + r * SU + n * 2;
                    *(uint32_t*)p = hi;
                    *(uint32_t*)(p + (AL_OFF - AH_OFF)) = lo;
                }
            }
    }
    stage_w(smem, Wb, 128, tid);
    __syncthreads();

    // ---- GEMM2 ----
#pragma unroll
    for (int mt = 0; mt < 2; mt++)
#pragma unroll
        for (int nt = 0; nt < 8; nt++)
#pragma unroll
            for (int c = 0; c < 4; c++) acc[mt][nt][c] = 0.f;

    gemm2t(acc, sbase, SU, 8, m0, n0, lane);

    // ---- epilogue 2: LN + relu (+ residual) -> out ----
    ln_stats(acc, smem, s_par, 384, m0, n0, cg, lane, mean, rstd);
    {
        const int grp = lane >> 2, qd = lane & 3;
#pragma unroll
        for (int mt = 0; mt < 2; mt++)
#pragma unroll
            for (int h = 0; h < 2; h++) {
                int r = m0 + mt * 16 + grp + h * 8;
                int row = row0 + r;
                if (row >= NODES) continue;
                float mu = mean[mt][h], rs = rstd[mt][h];
#pragma unroll
                for (int nt = 0; nt < 8; nt++) {
                    int n = n0 + nt * 8 + qd * 2;
                    int ci = h * 2;
                    float d0 = acc[mt][nt][ci], d1 = acc[mt][nt][ci + 1];
                    float v0 = fmaf((d0 - mu) * rs, s_par[512 + n], s_par[640 + n]);
                    float v1 = fmaf((d1 - mu) * rs, s_par[512 + n + 1], s_par[640 + n + 1]);
                    v0 = fmaxf(v0, 0.f); v1 = fmaxf(v1, 0.f);
                    if (br == 0) {
                        float2 xv = *(const float2*)(x + (size_t)row * 128 + n);
                        v0 += xv.x; v1 += xv.y;
                    }
                    *(float2*)(outb + (size_t)row * 128 + n) = make_float2(v0, v1);
                }
            }
    }
}

// ---------------- launch ----------------
extern "C" void kernel_launch(void* const* d_in, const int* in_sizes, int n_in,
                              void* d_out, int out_size) {
    const float* x    = (const float*)d_in[0];
    const float* pos  = (const float*)d_in[1];
    const int*   ei   = (const int*)d_in[2];
    const float* eps  = (const float*)d_in[3];
    const float* W1   = (const float*)d_in[4];
    const float* b1   = (const float*)d_in[5];
    const float* g1   = (const float*)d_in[6];
    const float* be1  = (const float*)d_in[7];
    const float* W2   = (const float*)d_in[8];
    const float* b2   = (const float*)d_in[9];
    const float* lng  = (const float*)d_in[10];
    const float* lnb  = (const float*)d_in[11];
    const float* epsp = (const float*)d_in[12];
    const float* W1p  = (const float*)d_in[13];
    const float* b1p  = (const float*)d_in[14];
    const float* g1p  = (const float*)d_in[15];
    const float* be1p = (const float*)d_in[16];
    const float* W2p  = (const float*)d_in[17];
    const float* b2p  = (const float*)d_in[18];
    const float* lnpg = (const float*)d_in[19];
    const float* lnpb = (const float*)d_in[20];
    float* out = (float*)d_out;

    zero_agg_kernel<<<(NODES * 192 / 4) / 256, 256>>>();
    scatter_kernel<<<EDGES / 8, 256>>>(x, pos, ei);

    cudaFuncSetAttribute(gin_mma_kernel,
                         cudaFuncAttributeMaxDynamicSharedMemorySize, SM_TOTAL);
    dim3 grid((NODES + 127) / 128, 2);
    gin_mma_kernel<<<grid, 256, SM_TOTAL>>>(
        x, pos, eps, W1, b1, g1, be1, W2, b2, lng, lnb,
        epsp, W1p, b1p, g1p, be1p, W2p, b2p, lnpg, lnpb, out);
}